// round 1
// baseline (speedup 1.0000x reference)
#include <cuda_runtime.h>

// Problem constants
#define Bb 8
#define Cc 256
#define HH 48
#define WW 48
#define NN (HH * WW)      // 2304
#define EPS_BN 1e-5f
#define KSPLIT 6
#define KCHUNK (NN / KSPLIT)  // 384

// Scratch (static device globals -- no runtime allocation)
__device__ float g_Q[Bb * Cc * NN];
__device__ float g_K[Bb * Cc * NN];
__device__ float g_V[Bb * Cc * NN];
__device__ float g_KVp[Bb * KSPLIT * Cc * Cc];  // split-K partials of K @ V^T
__device__ float g_KV[Bb * Cc * Cc];            // reduced, scaled by 1/N
__device__ float g_M[Bb * Cc * Cc];             // Wz @ KV^T

#define BK 16
#define LDA128 132   // 128 + 4 pad
#define LDA64  68    // 64 + 4 pad

// ---------------------------------------------------------------------------
// 128x128 tile SGEMM body: Y = A[M,K] @ B[K,Nn], row-major.
// 256 threads, 8x8 outputs/thread, float4 smem traffic.
// ---------------------------------------------------------------------------
__device__ __forceinline__ void gemm128_acc(
    const float* __restrict__ A, int lda,
    const float* __restrict__ B, int ldb,
    int Kdim, int m0, int n0,
    float acc[8][8], float* sbuf)
{
    float (*As)[LDA128] = (float (*)[LDA128])sbuf;
    float (*Bs)[LDA128] = (float (*)[LDA128])(sbuf + BK * LDA128);
    const int tid = threadIdx.x;
    const int tx = tid & 15;
    const int ty = tid >> 4;

    for (int k0 = 0; k0 < Kdim; k0 += BK) {
        // Load A tile: 128 rows x 16 k, transpose into As[k][m]
        {
            int row = tid >> 1;          // 0..127
            int half = tid & 1;          // 0..1
            const float* src = A + (m0 + row) * lda + k0 + half * 8;
            float4 v0 = *(const float4*)(src);
            float4 v1 = *(const float4*)(src + 4);
            int kk = half * 8;
            As[kk + 0][row] = v0.x; As[kk + 1][row] = v0.y;
            As[kk + 2][row] = v0.z; As[kk + 3][row] = v0.w;
            As[kk + 4][row] = v1.x; As[kk + 5][row] = v1.y;
            As[kk + 6][row] = v1.z; As[kk + 7][row] = v1.w;
        }
        // Load B tile: 16 rows x 128 n, direct
        {
            int row = tid >> 4;          // 0..15
            int c = tid & 15;            // 0..15
            const float* src = B + (k0 + row) * ldb + n0 + c * 8;
            float4 v0 = *(const float4*)(src);
            float4 v1 = *(const float4*)(src + 4);
            *(float4*)&Bs[row][c * 8]     = v0;
            *(float4*)&Bs[row][c * 8 + 4] = v1;
        }
        __syncthreads();
        #pragma unroll
        for (int kk = 0; kk < BK; kk++) {
            float4 a0 = *(const float4*)&As[kk][ty * 8];
            float4 a1 = *(const float4*)&As[kk][ty * 8 + 4];
            float4 b0 = *(const float4*)&Bs[kk][tx * 8];
            float4 b1 = *(const float4*)&Bs[kk][tx * 8 + 4];
            float a[8] = {a0.x, a0.y, a0.z, a0.w, a1.x, a1.y, a1.z, a1.w};
            float b[8] = {b0.x, b0.y, b0.z, b0.w, b1.x, b1.y, b1.z, b1.w};
            #pragma unroll
            for (int i = 0; i < 8; i++)
                #pragma unroll
                for (int j = 0; j < 8; j++)
                    acc[i][j] += a[i] * b[j];
        }
        __syncthreads();
    }
}

// ---------------------------------------------------------------------------
// 64x64 tile SGEMM body for Y = A @ B^T over inner range [kbeg,kend):
// Y[m,n] = sum_k A[m,k] * B[n,k]   (A: [M,Kin] ld=lda, B: [Nn,Kin] ld=ldb)
// 256 threads, 4x4 outputs/thread.
// ---------------------------------------------------------------------------
__device__ __forceinline__ void gemm64t_acc(
    const float* __restrict__ A, int lda,
    const float* __restrict__ B, int ldb,
    int kbeg, int kend, int m0, int n0,
    float acc[4][4], float* sbuf)
{
    float (*As)[LDA64] = (float (*)[LDA64])sbuf;
    float (*Bs)[LDA64] = (float (*)[LDA64])(sbuf + BK * LDA64);
    const int tid = threadIdx.x;
    const int tx = tid & 15;
    const int ty = tid >> 4;
    const int row = tid >> 2;   // 0..63
    const int q = tid & 3;      // 0..3

    for (int k0 = kbeg; k0 < kend; k0 += BK) {
        {
            float4 va = *(const float4*)(A + (m0 + row) * lda + k0 + q * 4);
            As[q * 4 + 0][row] = va.x; As[q * 4 + 1][row] = va.y;
            As[q * 4 + 2][row] = va.z; As[q * 4 + 3][row] = va.w;
            float4 vb = *(const float4*)(B + (n0 + row) * ldb + k0 + q * 4);
            Bs[q * 4 + 0][row] = vb.x; Bs[q * 4 + 1][row] = vb.y;
            Bs[q * 4 + 2][row] = vb.z; Bs[q * 4 + 3][row] = vb.w;
        }
        __syncthreads();
        #pragma unroll
        for (int kk = 0; kk < BK; kk++) {
            float4 a4 = *(const float4*)&As[kk][ty * 4];
            float4 b4 = *(const float4*)&Bs[kk][tx * 4];
            float a[4] = {a4.x, a4.y, a4.z, a4.w};
            float b[4] = {b4.x, b4.y, b4.z, b4.w};
            #pragma unroll
            for (int i = 0; i < 4; i++)
                #pragma unroll
                for (int j = 0; j < 4; j++)
                    acc[i][j] += a[i] * b[j];
        }
        __syncthreads();
    }
}

// ---------------------------------------------------------------------------
// Kernel 1: Q/K/V 1x1 convs.  grid(18, 2, 24): z = b*3 + which
// ---------------------------------------------------------------------------
__global__ __launch_bounds__(256) void qkv_gemm(
    const float* __restrict__ Qf, const float* __restrict__ KVf,
    const float* __restrict__ Wq, const float* __restrict__ Wk,
    const float* __restrict__ Wv)
{
    __shared__ float sbuf[2 * BK * LDA128];
    int bz = blockIdx.z;
    int b = bz / 3, which = bz - b * 3;
    const float* W = (which == 0) ? Wq : (which == 1) ? Wk : Wv;
    const float* X = ((which == 0) ? Qf : KVf) + (size_t)b * Cc * NN;
    float* Y = ((which == 0) ? g_Q : (which == 1) ? g_K : g_V) + (size_t)b * Cc * NN;
    int m0 = blockIdx.y * 128;
    int n0 = blockIdx.x * 128;

    float acc[8][8];
    #pragma unroll
    for (int i = 0; i < 8; i++)
        #pragma unroll
        for (int j = 0; j < 8; j++) acc[i][j] = 0.f;

    gemm128_acc(W, Cc, X, NN, Cc, m0, n0, acc, sbuf);

    int tx = threadIdx.x & 15, ty = threadIdx.x >> 4;
    #pragma unroll
    for (int i = 0; i < 8; i++) {
        float* dst = Y + (size_t)(m0 + ty * 8 + i) * NN + n0 + tx * 8;
        float4 o0 = {acc[i][0], acc[i][1], acc[i][2], acc[i][3]};
        float4 o1 = {acc[i][4], acc[i][5], acc[i][6], acc[i][7]};
        *(float4*)(dst)     = o0;
        *(float4*)(dst + 4) = o1;
    }
}

// ---------------------------------------------------------------------------
// Kernel 2: KV partials = K @ V^T over split-K chunks.  grid(4, 4, 48)
// ---------------------------------------------------------------------------
__global__ __launch_bounds__(256) void kv_gemm()
{
    __shared__ float sbuf[2 * BK * LDA64];
    int bz = blockIdx.z;
    int b = bz / KSPLIT, s = bz - b * KSPLIT;
    const float* Kp = g_K + (size_t)b * Cc * NN;
    const float* Vp = g_V + (size_t)b * Cc * NN;
    float* Y = g_KVp + (size_t)(b * KSPLIT + s) * Cc * Cc;
    int m0 = blockIdx.y * 64;
    int n0 = blockIdx.x * 64;

    float acc[4][4];
    #pragma unroll
    for (int i = 0; i < 4; i++)
        #pragma unroll
        for (int j = 0; j < 4; j++) acc[i][j] = 0.f;

    gemm64t_acc(Kp, NN, Vp, NN, s * KCHUNK, s * KCHUNK + KCHUNK, m0, n0, acc, sbuf);

    int tx = threadIdx.x & 15, ty = threadIdx.x >> 4;
    #pragma unroll
    for (int i = 0; i < 4; i++) {
        float* dst = Y + (size_t)(m0 + ty * 4 + i) * Cc + n0 + tx * 4;
        float4 o = {acc[i][0], acc[i][1], acc[i][2], acc[i][3]};
        *(float4*)dst = o;
    }
}

// ---------------------------------------------------------------------------
// Kernel 3: reduce split-K partials, scale by 1/N.  grid(2048)
// ---------------------------------------------------------------------------
__global__ __launch_bounds__(256) void kv_reduce()
{
    int i = blockIdx.x * 256 + threadIdx.x;
    int b = i >> 16;          // / (Cc*Cc)
    int r = i & 65535;
    float sum = 0.f;
    #pragma unroll
    for (int s = 0; s < KSPLIT; s++)
        sum += g_KVp[(size_t)(b * KSPLIT + s) * Cc * Cc + r];
    g_KV[i] = sum * (1.0f / (float)NN);
}

// ---------------------------------------------------------------------------
// Kernel 4: M[b] = Wz @ KV[b]^T  (M[o,c] = sum_d Wz[o,d] * KV[b][c,d])
// grid(4, 4, 8)
// ---------------------------------------------------------------------------
__global__ __launch_bounds__(256) void m_gemm(const float* __restrict__ Wz)
{
    __shared__ float sbuf[2 * BK * LDA64];
    int b = blockIdx.z;
    const float* KVb = g_KV + (size_t)b * Cc * Cc;
    float* Y = g_M + (size_t)b * Cc * Cc;
    int m0 = blockIdx.y * 64;
    int n0 = blockIdx.x * 64;

    float acc[4][4];
    #pragma unroll
    for (int i = 0; i < 4; i++)
        #pragma unroll
        for (int j = 0; j < 4; j++) acc[i][j] = 0.f;

    gemm64t_acc(Wz, Cc, KVb, Cc, 0, Cc, m0, n0, acc, sbuf);

    int tx = threadIdx.x & 15, ty = threadIdx.x >> 4;
    #pragma unroll
    for (int i = 0; i < 4; i++) {
        float* dst = Y + (size_t)(m0 + ty * 4 + i) * Cc + n0 + tx * 4;
        float4 o = {acc[i][0], acc[i][1], acc[i][2], acc[i][3]};
        *(float4*)dst = o;
    }
}

// ---------------------------------------------------------------------------
// Kernel 5: out = (M[b] @ Q[b]) * inv + bias + Qf   grid(18, 2, 8)
// ---------------------------------------------------------------------------
__global__ __launch_bounds__(256) void out_gemm(
    const float* __restrict__ Qf,
    const float* __restrict__ gamma, const float* __restrict__ beta,
    const float* __restrict__ mean,  const float* __restrict__ var,
    float* __restrict__ out)
{
    __shared__ float sbuf[2 * BK * LDA128];
    int b = blockIdx.z;
    const float* A = g_M + (size_t)b * Cc * Cc;
    const float* Bq = g_Q + (size_t)b * Cc * NN;
    const float* Qfb = Qf + (size_t)b * Cc * NN;
    float* Yb = out + (size_t)b * Cc * NN;
    int m0 = blockIdx.y * 128;
    int n0 = blockIdx.x * 128;

    float acc[8][8];
    #pragma unroll
    for (int i = 0; i < 8; i++)
        #pragma unroll
        for (int j = 0; j < 8; j++) acc[i][j] = 0.f;

    gemm128_acc(A, Cc, Bq, NN, Cc, m0, n0, acc, sbuf);

    int tx = threadIdx.x & 15, ty = threadIdx.x >> 4;
    #pragma unroll
    for (int i = 0; i < 8; i++) {
        int m = m0 + ty * 8 + i;
        float inv = gamma[m] * rsqrtf(var[m] + EPS_BN);
        float bias = beta[m] - mean[m] * inv;
        size_t off = (size_t)m * NN + n0 + tx * 8;
        float4 r0 = *(const float4*)(Qfb + off);
        float4 r1 = *(const float4*)(Qfb + off + 4);
        float4 o0 = {acc[i][0] * inv + bias + r0.x,
                     acc[i][1] * inv + bias + r0.y,
                     acc[i][2] * inv + bias + r0.z,
                     acc[i][3] * inv + bias + r0.w};
        float4 o1 = {acc[i][4] * inv + bias + r1.x,
                     acc[i][5] * inv + bias + r1.y,
                     acc[i][6] * inv + bias + r1.z,
                     acc[i][7] * inv + bias + r1.w};
        *(float4*)(Yb + off)     = o0;
        *(float4*)(Yb + off + 4) = o1;
    }
}

// ---------------------------------------------------------------------------
// Launch
// Inputs (metadata order): Q_feat_s, KV_feat_s, Wq, Wk, Wv, Wz,
//                          bn_gamma, bn_beta, bn_mean, bn_var
// ---------------------------------------------------------------------------
extern "C" void kernel_launch(void* const* d_in, const int* in_sizes, int n_in,
                              void* d_out, int out_size)
{
    const float* Qf    = (const float*)d_in[0];
    const float* KVf   = (const float*)d_in[1];
    const float* Wq    = (const float*)d_in[2];
    const float* Wk    = (const float*)d_in[3];
    const float* Wv    = (const float*)d_in[4];
    const float* Wz    = (const float*)d_in[5];
    const float* gamma = (const float*)d_in[6];
    const float* beta  = (const float*)d_in[7];
    const float* mean  = (const float*)d_in[8];
    const float* var   = (const float*)d_in[9];
    float* out = (float*)d_out;

    dim3 blk(256);

    // 1) Q, K, V = W @ X (three GEMMs, fused launch)
    qkv_gemm<<<dim3(NN / 128, Cc / 128, Bb * 3), blk>>>(Qf, KVf, Wq, Wk, Wv);

    // 2) KV partials = K @ V^T (split-K over N)
    kv_gemm<<<dim3(Cc / 64, Cc / 64, Bb * KSPLIT), blk>>>();

    // 3) reduce partials, scale by 1/N
    kv_reduce<<<dim3((Bb * Cc * Cc) / 256), blk>>>();

    // 4) M = Wz @ KV^T
    m_gemm<<<dim3(Cc / 64, Cc / 64, Bb), blk>>>(Wz);

    // 5) out = (M @ Q) * inv + bias + residual
    out_gemm<<<dim3(NN / 128, Cc / 128, Bb), blk>>>(Qf, gamma, beta, mean, var, out);
}

// round 3
// speedup vs baseline: 3.4845x; 3.4845x over previous
#include <cuda_runtime.h>
#include <cuda_bf16.h>
#include <cstdint>

// ---------------------------------------------------------------------------
// Problem constants
// ---------------------------------------------------------------------------
#define Bb 8
#define Cc 256
#define NN 2304
#define EPS_BN 1e-5f
#define NSPLIT 9                 // spatial split for K@V^T (2304 / 256)

#define SB_OFF 65536             // B tile SMEM offset (A tile = 64KB)
#define SMEM_TOTAL 196608        // 64KB A + 128KB B

// ---------------------------------------------------------------------------
// Scratch (static device globals)
// ---------------------------------------------------------------------------
__device__ __nv_bfloat16 g_Xq [Bb * NN * Cc];   // Q_feat transposed [b][n][c]
__device__ __nv_bfloat16 g_Xkv[Bb * NN * Cc];   // KV_feat transposed [b][n][c]
__device__ __nv_bfloat16 g_Qt [Bb * NN * Cc];   // Q   in [b][n][o]
__device__ __nv_bfloat16 g_K  [Bb * Cc * NN];   // K   in [b][o][n]
__device__ __nv_bfloat16 g_V  [Bb * Cc * NN];   // V   in [b][o][n]
__device__ __nv_bfloat16 g_KVp[Bb * NSPLIT * Cc * Cc]; // K@V^T split partials
__device__ __nv_bfloat16 g_KV [Bb * Cc * Cc];   // reduced, /N
__device__ __nv_bfloat16 g_M  [Bb * Cc * Cc];   // Wz @ KV^T  [b][o][c]
__device__ __nv_bfloat16 g_Wqb[Cc * Cc];
__device__ __nv_bfloat16 g_Wkb[Cc * Cc];
__device__ __nv_bfloat16 g_Wvb[Cc * Cc];
__device__ __nv_bfloat16 g_Wzb[Cc * Cc];

// ---------------------------------------------------------------------------
// PTX helpers (baseline ISA only -- no sm_103a-accelerated features)
// ---------------------------------------------------------------------------
__device__ __forceinline__ uint32_t s2u(const void* p) {
    uint32_t a;
    asm("{ .reg .u64 t; cvta.to.shared.u64 t, %1; cvt.u32.u64 %0, t; }"
        : "=r"(a) : "l"(p));
    return a;
}

__device__ __forceinline__ void ldsm4(uint32_t* r, uint32_t addr) {
    asm volatile(
        "ldmatrix.sync.aligned.m8n8.x4.shared.b16 {%0,%1,%2,%3}, [%4];"
        : "=r"(r[0]), "=r"(r[1]), "=r"(r[2]), "=r"(r[3]) : "r"(addr));
}

__device__ __forceinline__ void mma16816(float* d, const uint32_t* a,
                                         const uint32_t* b) {
    asm volatile(
        "mma.sync.aligned.m16n8k16.row.col.f32.bf16.bf16.f32 "
        "{%0,%1,%2,%3}, {%4,%5,%6,%7}, {%8,%9}, {%0,%1,%2,%3};"
        : "+f"(d[0]), "+f"(d[1]), "+f"(d[2]), "+f"(d[3])
        : "r"(a[0]), "r"(a[1]), "r"(a[2]), "r"(a[3]), "r"(b[0]), "r"(b[1]));
}

// ---------------------------------------------------------------------------
// Operand loader: GMEM [R rows x 256 bf16 cols, row stride ld] -> swizzled SMEM
// Row = 512B; 16B chunk index XOR'd with (row & 7) -> conflict-free ldmatrix.
// ---------------------------------------------------------------------------
__device__ __forceinline__ void load_tile(const __nv_bfloat16* __restrict__ src,
                                          int ld, int R, char* dst) {
    const int iters = R >> 3;
    const int tid = threadIdx.x;
#pragma unroll 4
    for (int it = 0; it < iters; it++) {
        int idx = it * 256 + tid;
        int row = idx >> 5;
        int c16 = idx & 31;                       // 16B chunk within row
        uint4 v = *(const uint4*)(src + (size_t)row * ld + c16 * 8);
        uint32_t bc = (uint32_t)(c16 << 4);
        uint32_t phys = (uint32_t)(row << 9) + (bc ^ (((uint32_t)row & 7u) << 4));
        *(uint4*)(dst + phys) = v;
    }
}

// ---------------------------------------------------------------------------
// GEMM core: acc[4][8][4] += A[128,256] @ B[256,256]^T  (both K-major bf16).
// 8 warps: warp (wm,wn) owns 64x64. K=256 in 16 k-steps of 16.
// ---------------------------------------------------------------------------
__device__ __forceinline__ void gemm_core(const __nv_bfloat16* __restrict__ A,
                                          int lda,
                                          const __nv_bfloat16* __restrict__ Bm,
                                          int ldb,
                                          float acc[4][8][4], char* sm,
                                          uint32_t su) {
    load_tile(A,  lda, 128, sm);
    load_tile(Bm, ldb, 256, sm + SB_OFF);
    __syncthreads();

    const int tid  = threadIdx.x;
    const int warp = tid >> 5, lane = tid & 31;
    const int wm = warp >> 2, wn = warp & 3;
    const int g  = lane >> 3, lr = lane & 7;

    // ldmatrix lane geometry (see fragment quadrant mapping)
    const uint32_t amask = (uint32_t)lr << 4;
    const uint32_t abase = su + (uint32_t)((wm * 64 + ((g & 1) << 3) + lr) << 9);
    const uint32_t abc0  = (uint32_t)((g >> 1) << 4);
    const uint32_t bbase = su + SB_OFF
                         + (uint32_t)((wn * 64 + ((g >> 1) << 3) + lr) << 9);
    const uint32_t bbc0  = (uint32_t)((g & 1) << 4);

#pragma unroll
    for (int ks = 0; ks < 16; ks++) {
        const uint32_t kb = (uint32_t)(ks << 5);
        uint32_t a[4][4];
#pragma unroll
        for (int i = 0; i < 4; i++)
            ldsm4(a[i], abase + (uint32_t)(i << 13) + ((abc0 + kb) ^ amask));
        uint32_t b[4][4];                 // b[jp] = {tile 2jp: b0,b1, tile 2jp+1: b0,b1}
#pragma unroll
        for (int jp = 0; jp < 4; jp++)
            ldsm4(b[jp], bbase + (uint32_t)(jp << 13) + ((bbc0 + kb) ^ amask));
#pragma unroll
        for (int i = 0; i < 4; i++)
#pragma unroll
            for (int j = 0; j < 8; j++)
                mma16816(acc[i][j], a[i], &b[j >> 1][(j & 1) * 2]);
    }
    (void)bbc0;
}

// ---------------------------------------------------------------------------
// Epilogue: acc -> bf16 GMEM tile (row stride ldo), direct fragment stores.
// d-frag: d0,d1 = row lane/4, cols 2*(lane%4)+{0,1}; d2,d3 = row+8.
// ---------------------------------------------------------------------------
__device__ __forceinline__ void epi_bf16(float acc[4][8][4],
                                         __nv_bfloat16* __restrict__ dst,
                                         int ldo) {
    const int tid = threadIdx.x;
    const int warp = tid >> 5, lane = tid & 31;
    const int wm = warp >> 2, wn = warp & 3;
    const int r0 = wm * 64 + (lane >> 2);
    const int c0 = wn * 64 + ((lane & 3) << 1);
#pragma unroll
    for (int i = 0; i < 4; i++) {
#pragma unroll
        for (int j = 0; j < 8; j++) {
            float* d = acc[i][j];
            int r = r0 + i * 16;
            int c = c0 + j * 8;
            uint32_t p0, p1;
            asm("cvt.rn.satfinite.bf16x2.f32 %0, %1, %2;"
                : "=r"(p0) : "f"(d[1]), "f"(d[0]));
            asm("cvt.rn.satfinite.bf16x2.f32 %0, %1, %2;"
                : "=r"(p1) : "f"(d[3]), "f"(d[2]));
            *(uint32_t*)(dst + (size_t)r * ldo + c)       = p0;
            *(uint32_t*)(dst + (size_t)(r + 8) * ldo + c) = p1;
        }
    }
}

// ---------------------------------------------------------------------------
// Epilogue for final output: out = acc*inv + bias + residual (all fp32).
// Rows = channels (m_base + rel), cols = spatial. Row stride NN.
// ---------------------------------------------------------------------------
__device__ __forceinline__ void epi_bn(float acc[4][8][4],
                                       const float* __restrict__ Qfb,
                                       float* __restrict__ outb, int m_base,
                                       const float* __restrict__ gamma,
                                       const float* __restrict__ beta,
                                       const float* __restrict__ mean,
                                       const float* __restrict__ var) {
    const int tid = threadIdx.x;
    const int warp = tid >> 5, lane = tid & 31;
    const int wm = warp >> 2, wn = warp & 3;
    const int r0 = wm * 64 + (lane >> 2);
    const int c0 = wn * 64 + ((lane & 3) << 1);
#pragma unroll
    for (int i = 0; i < 4; i++) {
        int r = r0 + i * 16;
#pragma unroll
        for (int half = 0; half < 2; half++) {
            int rr = r + half * 8;
            int gidx = m_base + rr;
            float inv  = gamma[gidx] * rsqrtf(var[gidx] + EPS_BN);
            float bias = beta[gidx] - mean[gidx] * inv;
#pragma unroll
            for (int j = 0; j < 8; j++) {
                int c = c0 + j * 8;
                float d0 = acc[i][j][half * 2];
                float d1 = acc[i][j][half * 2 + 1];
                float2 rq = *(const float2*)(Qfb + (size_t)rr * NN + c);
                float2 o;
                o.x = d0 * inv + bias + rq.x;
                o.y = d1 * inv + bias + rq.y;
                *(float2*)(outb + (size_t)rr * NN + c) = o;
            }
        }
    }
}

#define ZERO_ACC(acc)                                                         \
    do {                                                                      \
        _Pragma("unroll") for (int _i = 0; _i < 4; _i++)                      \
        _Pragma("unroll") for (int _j = 0; _j < 8; _j++)                      \
        _Pragma("unroll") for (int _q = 0; _q < 4; _q++)                      \
            acc[_i][_j][_q] = 0.f;                                            \
    } while (0)

// ---------------------------------------------------------------------------
// Kernel: transpose+convert inputs  [b][c][n] f32 -> [b][n][c] bf16
// ---------------------------------------------------------------------------
__global__ void k_convx(const float* __restrict__ Qf, const float* __restrict__ KVf) {
    __shared__ __nv_bfloat16 s[32][33];
    int z = blockIdx.z;
    int b = z >> 1, sel = z & 1;
    const float* src = (sel ? KVf : Qf) + (size_t)b * Cc * NN;
    __nv_bfloat16* dst = (sel ? g_Xkv : g_Xq) + (size_t)b * NN * Cc;
    int n0 = blockIdx.x * 32, c0 = blockIdx.y * 32;
    int tx = threadIdx.x, ty = threadIdx.y;
#pragma unroll
    for (int i = 0; i < 4; i++) {
        int c = c0 + ty + i * 8;
        s[ty + i * 8][tx] = __float2bfloat16(src[(size_t)c * NN + n0 + tx]);
    }
    __syncthreads();
#pragma unroll
    for (int i = 0; i < 4; i++) {
        int n = n0 + ty + i * 8;
        dst[(size_t)n * Cc + c0 + tx] = s[tx][ty + i * 8];
    }
}

// Kernel: convert all 4 weight matrices to bf16.
__global__ void k_convw(const float* __restrict__ Wq, const float* __restrict__ Wk,
                        const float* __restrict__ Wv, const float* __restrict__ Wz) {
    int i = blockIdx.x * 256 + threadIdx.x;
    int which = i >> 16, r = i & 65535;
    const float* src = (which == 0) ? Wq : (which == 1) ? Wk : (which == 2) ? Wv : Wz;
    __nv_bfloat16* dst = (which == 0) ? g_Wqb : (which == 1) ? g_Wkb
                                              : (which == 2) ? g_Wvb : g_Wzb;
    dst[r] = __float2bfloat16(src[r]);
}

// ---------------------------------------------------------------------------
// GEMM kernels
// ---------------------------------------------------------------------------
// K/V = W @ X, channel-major output [b][o][n].  grid 288
__global__ __launch_bounds__(256) void k_gemm1_kv() {
    extern __shared__ char sm[];
    uint32_t su = s2u(sm);
    int id = blockIdx.x;
    int b = id / 36, r = id % 36;
    int wsel = r / 18, r2 = r % 18, mt = r2 / 9, s = r2 % 9;
    const __nv_bfloat16* A  = (wsel ? g_Wvb : g_Wkb) + mt * 128 * Cc;
    const __nv_bfloat16* Bm = g_Xkv + (size_t)b * NN * Cc + (size_t)s * 256 * Cc;
    __nv_bfloat16* dst = (wsel ? g_V : g_K) + (size_t)b * Cc * NN
                         + (size_t)(mt * 128) * NN + s * 256;
    float acc[4][8][4];
    ZERO_ACC(acc);
    gemm_core(A, Cc, Bm, Cc, acc, sm, su);
    epi_bf16(acc, dst, NN);
}

// Q^T = X^T @ W^T, spatial-major output [b][n][o].  grid 144
__global__ __launch_bounds__(256) void k_gemm1_q() {
    extern __shared__ char sm[];
    uint32_t su = s2u(sm);
    int id = blockIdx.x;
    int b = id / 18, mt = id % 18;
    const __nv_bfloat16* A  = g_Xq + (size_t)b * NN * Cc + (size_t)mt * 128 * Cc;
    __nv_bfloat16* dst = g_Qt + (size_t)b * NN * Cc + (size_t)mt * 128 * Cc;
    float acc[4][8][4];
    ZERO_ACC(acc);
    gemm_core(A, Cc, g_Wqb, Cc, acc, sm, su);
    epi_bf16(acc, dst, Cc);
}

// KV partials = K @ V^T over 256-wide spatial chunks.  grid 144
__global__ __launch_bounds__(256) void k_gemm2() {
    extern __shared__ char sm[];
    uint32_t su = s2u(sm);
    int id = blockIdx.x;
    int b = id / 18, r = id % 18, mt = r / 9, s = r % 9;
    const __nv_bfloat16* A  = g_K + (size_t)b * Cc * NN + (size_t)(mt * 128) * NN + s * 256;
    const __nv_bfloat16* Bm = g_V + (size_t)b * Cc * NN + s * 256;
    __nv_bfloat16* dst = g_KVp + ((size_t)(b * NSPLIT + s) << 16) + (size_t)mt * 128 * Cc;
    float acc[4][8][4];
    ZERO_ACC(acc);
    gemm_core(A, NN, Bm, NN, acc, sm, su);
    epi_bf16(acc, dst, Cc);
}

// Reduce partials, scale by 1/N.
__global__ void k_reduce() {
    int i = blockIdx.x * 256 + threadIdx.x;
    int b = i >> 16, r = i & 65535;
    float s = 0.f;
#pragma unroll
    for (int p = 0; p < NSPLIT; p++)
        s += __bfloat162float(g_KVp[((size_t)(b * NSPLIT + p) << 16) + r]);
    g_KV[i] = __float2bfloat16(s * (1.0f / (float)NN));
}

// M = Wz @ KV^T.  grid 16
__global__ __launch_bounds__(256) void k_gemm3() {
    extern __shared__ char sm[];
    uint32_t su = s2u(sm);
    int id = blockIdx.x;
    int b = id >> 1, mt = id & 1;
    const __nv_bfloat16* A  = g_Wzb + mt * 128 * Cc;
    const __nv_bfloat16* Bm = g_KV + ((size_t)b << 16);
    __nv_bfloat16* dst = g_M + ((size_t)b << 16) + (size_t)mt * 128 * Cc;
    float acc[4][8][4];
    ZERO_ACC(acc);
    gemm_core(A, Cc, Bm, Cc, acc, sm, su);
    epi_bf16(acc, dst, Cc);
}

// out = (M @ Q) * inv + bias + residual.  grid 144
__global__ __launch_bounds__(256) void k_gemm4(const float* __restrict__ Qf,
                                               const float* __restrict__ gamma,
                                               const float* __restrict__ beta,
                                               const float* __restrict__ mean,
                                               const float* __restrict__ var,
                                               float* __restrict__ out) {
    extern __shared__ char sm[];
    uint32_t su = s2u(sm);
    int id = blockIdx.x;
    int b = id / 18, r = id % 18, mt = r & 1, s = r >> 1;
    const __nv_bfloat16* A  = g_M + ((size_t)b << 16) + (size_t)mt * 128 * Cc;
    const __nv_bfloat16* Bm = g_Qt + (size_t)b * NN * Cc + (size_t)s * 256 * Cc;
    size_t off = (size_t)b * Cc * NN + (size_t)(mt * 128) * NN + s * 256;
    float acc[4][8][4];
    ZERO_ACC(acc);
    gemm_core(A, Cc, Bm, Cc, acc, sm, su);
    epi_bn(acc, Qf + off, out + off, mt * 128, gamma, beta, mean, var);
}

// ---------------------------------------------------------------------------
// Launch
// ---------------------------------------------------------------------------
extern "C" void kernel_launch(void* const* d_in, const int* in_sizes, int n_in,
                              void* d_out, int out_size) {
    const float* Qf    = (const float*)d_in[0];
    const float* KVf   = (const float*)d_in[1];
    const float* Wq    = (const float*)d_in[2];
    const float* Wk    = (const float*)d_in[3];
    const float* Wv    = (const float*)d_in[4];
    const float* Wz    = (const float*)d_in[5];
    const float* gamma = (const float*)d_in[6];
    const float* beta  = (const float*)d_in[7];
    const float* mean  = (const float*)d_in[8];
    const float* var   = (const float*)d_in[9];
    float* out = (float*)d_out;

    static int attr_done = 0;
    if (!attr_done) {
        cudaFuncSetAttribute(k_gemm1_kv, cudaFuncAttributeMaxDynamicSharedMemorySize, SMEM_TOTAL);
        cudaFuncSetAttribute(k_gemm1_q,  cudaFuncAttributeMaxDynamicSharedMemorySize, SMEM_TOTAL);
        cudaFuncSetAttribute(k_gemm2,    cudaFuncAttributeMaxDynamicSharedMemorySize, SMEM_TOTAL);
        cudaFuncSetAttribute(k_gemm3,    cudaFuncAttributeMaxDynamicSharedMemorySize, SMEM_TOTAL);
        cudaFuncSetAttribute(k_gemm4,    cudaFuncAttributeMaxDynamicSharedMemorySize, SMEM_TOTAL);
        attr_done = 1;
    }

    k_convx<<<dim3(NN / 32, Cc / 32, Bb * 2), dim3(32, 8)>>>(Qf, KVf);
    k_convw<<<1024, 256>>>(Wq, Wk, Wv, Wz);
    k_gemm1_kv<<<288, 256, SMEM_TOTAL>>>();
    k_gemm1_q<<<144, 256, SMEM_TOTAL>>>();
    k_gemm2<<<144, 256, SMEM_TOTAL>>>();
    k_reduce<<<2048, 256>>>();
    k_gemm3<<<16, 256, SMEM_TOTAL>>>();
    k_gemm4<<<144, 256, SMEM_TOTAL>>>(Qf, gamma, beta, mean, var, out);
}

// round 5
// speedup vs baseline: 4.5238x; 1.2983x over previous
#include <cuda_runtime.h>
#include <cuda_bf16.h>
#include <cstdint>

// ---------------------------------------------------------------------------
// Problem constants
// ---------------------------------------------------------------------------
#define Bb 8
#define Cc 256
#define NN 2304
#define EPS_BN 1e-5f
#define NSPLIT 9                 // spatial split for K@V^T (2304 / 256)

#define CH 64                    // K-chunk width (elements)
#define STG_A (128 * 128)        // A chunk bytes: 128 rows x 128B
#define STG_B (256 * 128)        // B chunk bytes: 256 rows x 128B
#define STG (STG_A + STG_B)      // 49152 per stage
#define SMEM_TOTAL (2 * STG)     // 98304 (double buffered)

// ---------------------------------------------------------------------------
// Scratch (static device globals)
// ---------------------------------------------------------------------------
__device__ __nv_bfloat16 g_Xq [Bb * NN * Cc];   // Q_feat transposed [b][n][c]
__device__ __nv_bfloat16 g_Xkv[Bb * NN * Cc];   // KV_feat transposed [b][n][c]
__device__ __nv_bfloat16 g_Qt [Bb * NN * Cc];   // Q   in [b][n][o]
__device__ __nv_bfloat16 g_K  [Bb * Cc * NN];   // K   in [b][o][n]
__device__ __nv_bfloat16 g_V  [Bb * Cc * NN];   // V   in [b][o][n]
__device__ __nv_bfloat16 g_KVp[Bb * NSPLIT * Cc * Cc]; // K@V^T split partials
__device__ __nv_bfloat16 g_KV [Bb * Cc * Cc];   // reduced, /N
__device__ __nv_bfloat16 g_M  [Bb * Cc * Cc];   // Wz @ KV^T  [b][o][c]
__device__ __nv_bfloat16 g_Wqb[Cc * Cc];
__device__ __nv_bfloat16 g_Wkb[Cc * Cc];
__device__ __nv_bfloat16 g_Wvb[Cc * Cc];
__device__ __nv_bfloat16 g_Wzb[Cc * Cc];

// ---------------------------------------------------------------------------
// PTX helpers (baseline ISA only; no sm_103a-accelerated features)
// ---------------------------------------------------------------------------
__device__ __forceinline__ uint32_t s2u(const void* p) {
    uint32_t a;
    asm("{ .reg .u64 t; cvta.to.shared.u64 t, %1; cvt.u32.u64 %0, t; }"
        : "=r"(a) : "l"(p));
    return a;
}

__device__ __forceinline__ void ldsm4(uint32_t* r, uint32_t addr) {
    asm volatile(
        "ldmatrix.sync.aligned.m8n8.x4.shared.b16 {%0,%1,%2,%3}, [%4];"
        : "=r"(r[0]), "=r"(r[1]), "=r"(r[2]), "=r"(r[3]) : "r"(addr));
}

__device__ __forceinline__ void mma16816(float* d, const uint32_t* a,
                                         const uint32_t* b) {
    asm volatile(
        "mma.sync.aligned.m16n8k16.row.col.f32.bf16.bf16.f32 "
        "{%0,%1,%2,%3}, {%4,%5,%6,%7}, {%8,%9}, {%0,%1,%2,%3};"
        : "+f"(d[0]), "+f"(d[1]), "+f"(d[2]), "+f"(d[3])
        : "r"(a[0]), "r"(a[1]), "r"(a[2]), "r"(a[3]), "r"(b[0]), "r"(b[1]));
}

__device__ __forceinline__ void cp16(uint32_t dst, const void* src) {
    asm volatile("cp.async.cg.shared.global [%0], [%1], 16;"
                 :: "r"(dst), "l"(src));
}

// ---------------------------------------------------------------------------
// Async chunk loader: GMEM [R rows x 64 bf16, row stride ld] -> swizzled SMEM
// stage. Row = 128B (8 x 16B chunks), chunk index XOR (row & 7).
// Each 8-thread group fills one full 128B row -> conflict-free phases.
// ---------------------------------------------------------------------------
__device__ __forceinline__ void load_chunk(const __nv_bfloat16* __restrict__ src,
                                           int ld, int R, uint32_t dstu) {
    const int tid = threadIdx.x;
    const int iters = R >> 5;            // R*8 16B-chunks / 256 threads
#pragma unroll
    for (int it = 0; it < iters; it++) {
        int idx = it * 256 + tid;
        int row = idx >> 3;
        int c16 = idx & 7;
        uint32_t phys = ((uint32_t)row << 7) +
                        (((uint32_t)c16 ^ ((uint32_t)row & 7u)) << 4);
        cp16(dstu + phys, src + (size_t)row * ld + c16 * 8);
    }
}

// ---------------------------------------------------------------------------
// Compute one 64-wide k-chunk: acc[4][8][4] += A_chunk @ B_chunk^T
// (warp (wm,wn) owns 64x64 of the 128x256 D tile)
// ---------------------------------------------------------------------------
__device__ __forceinline__ void compute_chunk(float acc[4][8][4], uint32_t sbuf,
                                              uint32_t aoff, uint32_t acol,
                                              uint32_t boff, uint32_t bcol,
                                              uint32_t xmask) {
#pragma unroll
    for (int k2 = 0; k2 < 4; k2++) {
        const uint32_t kb = (uint32_t)(k2 << 5);
        uint32_t a[4][4];
#pragma unroll
        for (int i = 0; i < 4; i++)
            ldsm4(a[i], sbuf + aoff + (uint32_t)(i << 11) + ((acol + kb) ^ xmask));
        uint32_t b[4][4];
#pragma unroll
        for (int jp = 0; jp < 4; jp++)
            ldsm4(b[jp], sbuf + boff + (uint32_t)(jp << 11) + ((bcol + kb) ^ xmask));
#pragma unroll
        for (int i = 0; i < 4; i++)
#pragma unroll
            for (int j = 0; j < 8; j++)
                mma16816(acc[i][j], a[i], &b[j >> 1][(j & 1) * 2]);
    }
}

// ---------------------------------------------------------------------------
// Pipelined GEMM core: acc += A[128,256] @ B[256,256]^T, both K-major bf16.
// Double-buffered cp.async over 4 k-chunks of 64.
// ---------------------------------------------------------------------------
__device__ __forceinline__ void gemm_core(const __nv_bfloat16* __restrict__ A,
                                          int lda,
                                          const __nv_bfloat16* __restrict__ Bm,
                                          int ldb,
                                          float acc[4][8][4], uint32_t su) {
    const int tid  = threadIdx.x;
    const int warp = tid >> 5, lane = tid & 31;
    const int wm = warp >> 2, wn = warp & 3;
    const int g  = lane >> 3, lr = lane & 7;

    const uint32_t xmask = (uint32_t)lr << 4;
    const uint32_t aoff  = (uint32_t)((wm * 64 + ((g & 1) << 3) + lr) << 7);
    const uint32_t acol  = (uint32_t)((g >> 1) << 4);
    const uint32_t boff  = STG_A + (uint32_t)((wn * 64 + ((g >> 1) << 3) + lr) << 7);
    const uint32_t bcol  = (uint32_t)((g & 1) << 4);

    // prologue: chunk 0 -> stage 0
    load_chunk(A,  lda, 128, su);
    load_chunk(Bm, ldb, 256, su + STG_A);
    asm volatile("cp.async.commit_group;");

#pragma unroll
    for (int ks = 0; ks < 4; ks++) {
        if (ks < 3) {
            uint32_t nbuf = su + (uint32_t)(((ks + 1) & 1) * STG);
            load_chunk(A  + (ks + 1) * CH, lda, 128, nbuf);
            load_chunk(Bm + (ks + 1) * CH, ldb, 256, nbuf + STG_A);
            asm volatile("cp.async.commit_group;");
            asm volatile("cp.async.wait_group 1;");
        } else {
            asm volatile("cp.async.wait_group 0;");
        }
        __syncthreads();
        compute_chunk(acc, su + (uint32_t)((ks & 1) * STG),
                      aoff, acol, boff, bcol, xmask);
        __syncthreads();
    }
}

// ---------------------------------------------------------------------------
// Epilogue: acc -> bf16 GMEM tile (row stride ldo), direct fragment stores.
// ---------------------------------------------------------------------------
__device__ __forceinline__ void epi_bf16(float acc[4][8][4],
                                         __nv_bfloat16* __restrict__ dst,
                                         int ldo) {
    const int tid = threadIdx.x;
    const int warp = tid >> 5, lane = tid & 31;
    const int wm = warp >> 2, wn = warp & 3;
    const int r0 = wm * 64 + (lane >> 2);
    const int c0 = wn * 64 + ((lane & 3) << 1);
#pragma unroll
    for (int i = 0; i < 4; i++) {
#pragma unroll
        for (int j = 0; j < 8; j++) {
            float* d = acc[i][j];
            int r = r0 + i * 16;
            int c = c0 + j * 8;
            uint32_t p0, p1;
            asm("cvt.rn.satfinite.bf16x2.f32 %0, %1, %2;"
                : "=r"(p0) : "f"(d[1]), "f"(d[0]));
            asm("cvt.rn.satfinite.bf16x2.f32 %0, %1, %2;"
                : "=r"(p1) : "f"(d[3]), "f"(d[2]));
            *(uint32_t*)(dst + (size_t)r * ldo + c)       = p0;
            *(uint32_t*)(dst + (size_t)(r + 8) * ldo + c) = p1;
        }
    }
}

// ---------------------------------------------------------------------------
// Epilogue for final output: out = acc*inv + bias + residual (all fp32).
// ---------------------------------------------------------------------------
__device__ __forceinline__ void epi_bn(float acc[4][8][4],
                                       const float* __restrict__ Qfb,
                                       float* __restrict__ outb, int m_base,
                                       const float* __restrict__ gamma,
                                       const float* __restrict__ beta,
                                       const float* __restrict__ mean,
                                       const float* __restrict__ var) {
    const int tid = threadIdx.x;
    const int warp = tid >> 5, lane = tid & 31;
    const int wm = warp >> 2, wn = warp & 3;
    const int r0 = wm * 64 + (lane >> 2);
    const int c0 = wn * 64 + ((lane & 3) << 1);
#pragma unroll
    for (int i = 0; i < 4; i++) {
        int r = r0 + i * 16;
#pragma unroll
        for (int half = 0; half < 2; half++) {
            int rr = r + half * 8;
            int gidx = m_base + rr;
            float inv  = gamma[gidx] * rsqrtf(var[gidx] + EPS_BN);
            float bias = beta[gidx] - mean[gidx] * inv;
#pragma unroll
            for (int j = 0; j < 8; j++) {
                int c = c0 + j * 8;
                float d0 = acc[i][j][half * 2];
                float d1 = acc[i][j][half * 2 + 1];
                float2 rq = *(const float2*)(Qfb + (size_t)rr * NN + c);
                float2 o;
                o.x = d0 * inv + bias + rq.x;
                o.y = d1 * inv + bias + rq.y;
                *(float2*)(outb + (size_t)rr * NN + c) = o;
            }
        }
    }
}

#define ZERO_ACC(acc)                                                         \
    do {                                                                      \
        _Pragma("unroll") for (int _i = 0; _i < 4; _i++)                      \
        _Pragma("unroll") for (int _j = 0; _j < 8; _j++)                      \
        _Pragma("unroll") for (int _q = 0; _q < 4; _q++)                      \
            acc[_i][_j][_q] = 0.f;                                            \
    } while (0)

// ---------------------------------------------------------------------------
// Kernel: transpose+convert inputs  [b][c][n] f32 -> [b][n][c] bf16
// ---------------------------------------------------------------------------
__global__ void k_convx(const float* __restrict__ Qf, const float* __restrict__ KVf) {
    __shared__ __nv_bfloat16 s[32][33];
    int z = blockIdx.z;
    int b = z >> 1, sel = z & 1;
    const float* src = (sel ? KVf : Qf) + (size_t)b * Cc * NN;
    __nv_bfloat16* dst = (sel ? g_Xkv : g_Xq) + (size_t)b * NN * Cc;
    int n0 = blockIdx.x * 32, c0 = blockIdx.y * 32;
    int tx = threadIdx.x, ty = threadIdx.y;
#pragma unroll
    for (int i = 0; i < 4; i++) {
        int c = c0 + ty + i * 8;
        s[ty + i * 8][tx] = __float2bfloat16(src[(size_t)c * NN + n0 + tx]);
    }
    __syncthreads();
#pragma unroll
    for (int i = 0; i < 4; i++) {
        int n = n0 + ty + i * 8;
        dst[(size_t)n * Cc + c0 + tx] = s[tx][ty + i * 8];
    }
}

// Kernel: convert all 4 weight matrices to bf16.
__global__ void k_convw(const float* __restrict__ Wq, const float* __restrict__ Wk,
                        const float* __restrict__ Wv, const float* __restrict__ Wz) {
    int i = blockIdx.x * 256 + threadIdx.x;
    int which = i >> 16, r = i & 65535;
    const float* src = (which == 0) ? Wq : (which == 1) ? Wk : (which == 2) ? Wv : Wz;
    __nv_bfloat16* dst = (which == 0) ? g_Wqb : (which == 1) ? g_Wkb
                                              : (which == 2) ? g_Wvb : g_Wzb;
    dst[r] = __float2bfloat16(src[r]);
}

// ---------------------------------------------------------------------------
// GEMM kernels
// ---------------------------------------------------------------------------
// Merged QKV: blocks 0..287 produce K/V (channel-major), 288..431 produce
// Q^T (spatial-major).  grid 432
__global__ __launch_bounds__(256) void k_gemm1() {
    extern __shared__ char sm[];
    uint32_t su = s2u(sm);
    int id = blockIdx.x;
    const __nv_bfloat16 *A, *Bm;
    __nv_bfloat16* dst;
    int ldo;
    if (id < 288) {
        int b = id / 36, r = id % 36;
        int wsel = r / 18, r2 = r % 18, mt = r2 / 9, s = r2 % 9;
        A   = (wsel ? g_Wvb : g_Wkb) + mt * 128 * Cc;
        Bm  = g_Xkv + (size_t)b * NN * Cc + (size_t)s * 256 * Cc;
        dst = (wsel ? g_V : g_K) + (size_t)b * Cc * NN
              + (size_t)(mt * 128) * NN + s * 256;
        ldo = NN;
    } else {
        int id2 = id - 288;
        int b = id2 / 18, mt = id2 % 18;
        A   = g_Xq + (size_t)b * NN * Cc + (size_t)mt * 128 * Cc;
        Bm  = g_Wqb;
        dst = g_Qt + (size_t)b * NN * Cc + (size_t)mt * 128 * Cc;
        ldo = Cc;
    }
    float acc[4][8][4];
    ZERO_ACC(acc);
    gemm_core(A, Cc, Bm, Cc, acc, su);
    epi_bf16(acc, dst, ldo);
}

// KV partials = K @ V^T over 256-wide spatial chunks.  grid 144
__global__ __launch_bounds__(256) void k_gemm2() {
    extern __shared__ char sm[];
    uint32_t su = s2u(sm);
    int id = blockIdx.x;
    int b = id / 18, r = id % 18, mt = r / 9, s = r % 9;
    const __nv_bfloat16* A  = g_K + (size_t)b * Cc * NN + (size_t)(mt * 128) * NN + s * 256;
    const __nv_bfloat16* Bm = g_V + (size_t)b * Cc * NN + s * 256;
    __nv_bfloat16* dst = g_KVp + ((size_t)(b * NSPLIT + s) << 16) + (size_t)mt * 128 * Cc;
    float acc[4][8][4];
    ZERO_ACC(acc);
    gemm_core(A, NN, Bm, NN, acc, su);
    epi_bf16(acc, dst, Cc);
}

// Reduce partials, scale by 1/N.
__global__ void k_reduce() {
    int i = blockIdx.x * 256 + threadIdx.x;
    int b = i >> 16, r = i & 65535;
    float s = 0.f;
#pragma unroll
    for (int p = 0; p < NSPLIT; p++)
        s += __bfloat162float(g_KVp[((size_t)(b * NSPLIT + p) << 16) + r]);
    g_KV[i] = __float2bfloat16(s * (1.0f / (float)NN));
}

// M = Wz @ KV^T.  grid 16
__global__ __launch_bounds__(256) void k_gemm3() {
    extern __shared__ char sm[];
    uint32_t su = s2u(sm);
    int id = blockIdx.x;
    int b = id >> 1, mt = id & 1;
    const __nv_bfloat16* A  = g_Wzb + mt * 128 * Cc;
    const __nv_bfloat16* Bm = g_KV + ((size_t)b << 16);
    __nv_bfloat16* dst = g_M + ((size_t)b << 16) + (size_t)mt * 128 * Cc;
    float acc[4][8][4];
    ZERO_ACC(acc);
    gemm_core(A, Cc, Bm, Cc, acc, su);
    epi_bf16(acc, dst, Cc);
}

// out = (M @ Q) * inv + bias + residual.  grid 144
__global__ __launch_bounds__(256) void k_gemm4(const float* __restrict__ Qf,
                                               const float* __restrict__ gamma,
                                               const float* __restrict__ beta,
                                               const float* __restrict__ mean,
                                               const float* __restrict__ var,
                                               float* __restrict__ out) {
    extern __shared__ char sm[];
    uint32_t su = s2u(sm);
    int id = blockIdx.x;
    int b = id / 18, r = id % 18, mt = r & 1, s = r >> 1;
    const __nv_bfloat16* A  = g_M + ((size_t)b << 16) + (size_t)mt * 128 * Cc;
    const __nv_bfloat16* Bm = g_Qt + (size_t)b * NN * Cc + (size_t)s * 256 * Cc;
    size_t off = (size_t)b * Cc * NN + (size_t)(mt * 128) * NN + s * 256;
    float acc[4][8][4];
    ZERO_ACC(acc);
    gemm_core(A, Cc, Bm, Cc, acc, su);
    epi_bn(acc, Qf + off, out + off, mt * 128, gamma, beta, mean, var);
}

// ---------------------------------------------------------------------------
// Launch
// ---------------------------------------------------------------------------
extern "C" void kernel_launch(void* const* d_in, const int* in_sizes, int n_in,
                              void* d_out, int out_size) {
    const float* Qf    = (const float*)d_in[0];
    const float* KVf   = (const float*)d_in[1];
    const float* Wq    = (const float*)d_in[2];
    const float* Wk    = (const float*)d_in[3];
    const float* Wv    = (const float*)d_in[4];
    const float* Wz    = (const float*)d_in[5];
    const float* gamma = (const float*)d_in[6];
    const float* beta  = (const float*)d_in[7];
    const float* mean  = (const float*)d_in[8];
    const float* var   = (const float*)d_in[9];
    float* out = (float*)d_out;

    cudaFuncSetAttribute(k_gemm1, cudaFuncAttributeMaxDynamicSharedMemorySize, SMEM_TOTAL);
    cudaFuncSetAttribute(k_gemm2, cudaFuncAttributeMaxDynamicSharedMemorySize, SMEM_TOTAL);
    cudaFuncSetAttribute(k_gemm3, cudaFuncAttributeMaxDynamicSharedMemorySize, SMEM_TOTAL);
    cudaFuncSetAttribute(k_gemm4, cudaFuncAttributeMaxDynamicSharedMemorySize, SMEM_TOTAL);

    k_convx<<<dim3(NN / 32, Cc / 32, Bb * 2), dim3(32, 8)>>>(Qf, KVf);
    k_convw<<<1024, 256>>>(Wq, Wk, Wv, Wz);
    k_gemm1<<<432, 256, SMEM_TOTAL>>>();
    k_gemm2<<<144, 256, SMEM_TOTAL>>>();
    k_reduce<<<2048, 256>>>();
    k_gemm3<<<16, 256, SMEM_TOTAL>>>();
    k_gemm4<<<144, 256, SMEM_TOTAL>>>(Qf, gamma, beta, mean, var, out);
}